// round 6
// baseline (speedup 1.0000x reference)
#include <cuda_runtime.h>
#include <cstdint>

#define L_SEQ 2048
#define D_DIM 768
#define K_F   16
#define NFFT  4096
#define KU    3
#define C_CONV (2 * K_F * D_DIM)          // 24576
#define C_TOT  (C_CONV + KU * D_DIM)      // 26880
#define NKT    (C_TOT / 16)               // 1680

__device__ __align__(16) float  g_Ubig[(size_t)C_TOT * L_SEQ];   // (C, L), tf32-rounded
__device__ __align__(16) float  g_Mbig[(size_t)C_TOT * D_DIM];   // (C, O), tf32-rounded
__device__ __align__(16) float2 g_Z[D_DIM * NFFT];
__device__ __align__(16) float2 g_V[K_F * NFFT];
__device__ __align__(16) float2 g_tw[NFFT];

__device__ __forceinline__ float2 cadd(float2 a, float2 b) { return make_float2(a.x + b.x, a.y + b.y); }
__device__ __forceinline__ float2 csub(float2 a, float2 b) { return make_float2(a.x - b.x, a.y - b.y); }
__device__ __forceinline__ float2 cmul(float2 a, float2 b) {
    return make_float2(a.x * b.x - a.y * b.y, a.x * b.y + a.y * b.x);
}
__device__ __forceinline__ float2 cmulconj(float2 a, float2 w) {
    return make_float2(a.x * w.x + a.y * w.y, a.y * w.x - a.x * w.y);
}
__device__ __forceinline__ float to_tf32(float x) {
    float r; asm("cvt.rna.tf32.f32 %0, %1;" : "=f"(r) : "f"(x)); return r;
}
__device__ __forceinline__ int sphys(int i) { return i + (i >> 4) + (i >> 8); }
#define SMEM_FFT 4368

__global__ void k_twiddle() {
    int j = blockIdx.x * blockDim.x + threadIdx.x;
    if (j < NFFT) {
        float s, c;
        sincospif(-2.0f * (float)j / (float)NFFT, &s, &c);
        g_tw[j] = make_float2(c, s);
    }
}

// ---- radix-4 butterflies ----
__device__ __forceinline__ void bf4_dif(float2& e0, float2& e1, float2& e2, float2& e3,
                                        float2 w1, float2 w2, float2 w3) {
    float2 t0 = cadd(e0, e2), t1 = csub(e0, e2);
    float2 t2 = cadd(e1, e3), t3 = csub(e1, e3);
    float2 t3m = make_float2(t3.y, -t3.x);
    e0 = cadd(t0, t2); e1 = cmul(cadd(t1, t3m), w1);
    e2 = cmul(csub(t0, t2), w2); e3 = cmul(csub(t1, t3m), w3);
}
__device__ __forceinline__ void bf4_dif_nw(float2& e0, float2& e1, float2& e2, float2& e3) {
    float2 t0 = cadd(e0, e2), t1 = csub(e0, e2);
    float2 t2 = cadd(e1, e3), t3 = csub(e1, e3);
    float2 t3m = make_float2(t3.y, -t3.x);
    e0 = cadd(t0, t2); e1 = cadd(t1, t3m); e2 = csub(t0, t2); e3 = csub(t1, t3m);
}
__device__ __forceinline__ void bf4_dit(float2& e0, float2& e1, float2& e2, float2& e3,
                                        float2 w1, float2 w2, float2 w3) {
    float2 u1 = cmulconj(e1, w1), u2 = cmulconj(e2, w2), u3 = cmulconj(e3, w3);
    float2 t0 = cadd(e0, u2), t1 = csub(e0, u2);
    float2 t2 = cadd(u1, u3), t3 = csub(u1, u3);
    float2 it3 = make_float2(-t3.y, t3.x);
    e0 = cadd(t0, t2); e1 = cadd(t1, it3); e2 = csub(t0, t2); e3 = csub(t1, it3);
}
__device__ __forceinline__ void bf4_dit_nw(float2& e0, float2& e1, float2& e2, float2& e3) {
    float2 t0 = cadd(e0, e2), t1 = csub(e0, e2);
    float2 t2 = cadd(e1, e3), t3 = csub(e1, e3);
    float2 it3 = make_float2(-t3.y, t3.x);
    e0 = cadd(t0, t2); e1 = cadd(t1, it3); e2 = csub(t0, t2); e3 = csub(t1, it3);
}

// Fused two radix-4 stages on r[16]; r[a*4+b] at offsets a*Q + b*Q2 (Q=4*Q2 elements apart in-stage).
template <int Q2, int STEP, int HT>
__device__ __forceinline__ void fwd_pass(float2* r, int j) {
    #pragma unroll
    for (int b = 0; b < 4; b++) {
        float2 w1 = g_tw[(j + b * Q2) * STEP];
        float2 w2 = cmul(w1, w1), w3 = cmul(w2, w1);
        bf4_dif(r[b], r[4 + b], r[8 + b], r[12 + b], w1, w2, w3);
    }
    if (HT) {
        #pragma unroll
        for (int a = 0; a < 4; a++) bf4_dif_nw(r[4 * a], r[4 * a + 1], r[4 * a + 2], r[4 * a + 3]);
    } else {
        float2 w1 = g_tw[j * STEP * 4];
        float2 w2 = cmul(w1, w1), w3 = cmul(w2, w1);
        #pragma unroll
        for (int a = 0; a < 4; a++) bf4_dif(r[4 * a], r[4 * a + 1], r[4 * a + 2], r[4 * a + 3], w1, w2, w3);
    }
}
template <int Q2, int STEP, int HT>
__device__ __forceinline__ void inv_pass(float2* r, int j) {
    if (HT) {
        #pragma unroll
        for (int a = 0; a < 4; a++) bf4_dit_nw(r[4 * a], r[4 * a + 1], r[4 * a + 2], r[4 * a + 3]);
    } else {
        float2 w1 = g_tw[j * STEP * 4];
        float2 w2 = cmul(w1, w1), w3 = cmul(w2, w1);
        #pragma unroll
        for (int a = 0; a < 4; a++) bf4_dit(r[4 * a], r[4 * a + 1], r[4 * a + 2], r[4 * a + 3], w1, w2, w3);
    }
    #pragma unroll
    for (int b = 0; b < 4; b++) {
        float2 w1 = g_tw[(j + b * Q2) * STEP];
        float2 w2 = cmul(w1, w1), w3 = cmul(w2, w1);
        bf4_dit(r[b], r[4 + b], r[8 + b], r[12 + b], w1, w2, w3);
    }
}

// ---- forward FFT: 768 packed x-channels + 16 phi-channels, 3 register passes ----
__global__ void __launch_bounds__(256) k_fft_fwd(const float* __restrict__ x,
                                                 const float* __restrict__ phi) {
    __shared__ float2 S[SMEM_FFT];
    const int blk = blockIdx.x, tid = threadIdx.x;
    float2 r[16];
    // pass 0: stages 0,1 — elems tid + a*1024 + b*256, straight from gmem
    #pragma unroll
    for (int a = 0; a < 4; a++)
        #pragma unroll
        for (int b = 0; b < 4; b++) {
            int idx = tid + a * 1024 + b * 256;
            if (blk < D_DIM) {
                float v = (idx < L_SEQ) ? __ldg(x + (size_t)idx * D_DIM + blk) : 0.0f;
                r[a * 4 + b] = make_float2(v, (idx & 1) ? -v : v);
            } else {
                float v = (idx < L_SEQ) ? __ldg(phi + (size_t)idx * K_F + (blk - D_DIM)) : 0.0f;
                r[a * 4 + b] = make_float2(v, 0.0f);
            }
        }
    fwd_pass<256, 1, 0>(r, tid);
    #pragma unroll
    for (int a = 0; a < 4; a++)
        #pragma unroll
        for (int b = 0; b < 4; b++) S[sphys(tid + a * 1024 + b * 256)] = r[a * 4 + b];
    __syncthreads();
    // pass 1: stages 2,3 — base g*256+j, offs a*64 + b*16
    {
        const int g = tid >> 4, j = tid & 15, base = g * 256 + j;
        #pragma unroll
        for (int a = 0; a < 4; a++)
            #pragma unroll
            for (int b = 0; b < 4; b++) r[a * 4 + b] = S[sphys(base + a * 64 + b * 16)];
        fwd_pass<16, 16, 0>(r, j);
        #pragma unroll
        for (int a = 0; a < 4; a++)
            #pragma unroll
            for (int b = 0; b < 4; b++) S[sphys(base + a * 64 + b * 16)] = r[a * 4 + b];
    }
    __syncthreads();
    // pass 2: stages 4,5 — base tid*16, offs a*4 + b
    {
        const int base = tid * 16;
        #pragma unroll
        for (int a = 0; a < 4; a++)
            #pragma unroll
            for (int b = 0; b < 4; b++) r[a * 4 + b] = S[sphys(base + a * 4 + b)];
        fwd_pass<1, 256, 1>(r, 0);
        #pragma unroll
        for (int a = 0; a < 4; a++)
            #pragma unroll
            for (int b = 0; b < 4; b++) S[sphys(base + a * 4 + b)] = r[a * 4 + b];
    }
    __syncthreads();
    float2* out = (blk < D_DIM) ? (g_Z + (size_t)blk * NFFT) : (g_V + (size_t)(blk - D_DIM) * NFFT);
    for (int t = tid; t < NFFT; t += 256) out[t] = S[sphys(t)];
}

// ---- per-(k,d): pointwise V*Z then inverse FFT (3 register passes), write tf32 ----
__global__ void __launch_bounds__(256) k_conv_inv() {
    __shared__ float2 S[SMEM_FFT];
    const int blk = blockIdx.x;
    const int k = blk / D_DIM, d = blk - k * D_DIM;
    const int tid = threadIdx.x;
    const float2* Z = g_Z + (size_t)d * NFFT;
    const float2* V = g_V + (size_t)k * NFFT;
    for (int t = tid; t < NFFT; t += 256) S[sphys(t)] = cmul(Z[t], V[t]);
    __syncthreads();
    float2 r[16];
    {   // inverse of fwd pass 2
        const int base = tid * 16;
        #pragma unroll
        for (int a = 0; a < 4; a++)
            #pragma unroll
            for (int b = 0; b < 4; b++) r[a * 4 + b] = S[sphys(base + a * 4 + b)];
        inv_pass<1, 256, 1>(r, 0);
        #pragma unroll
        for (int a = 0; a < 4; a++)
            #pragma unroll
            for (int b = 0; b < 4; b++) S[sphys(base + a * 4 + b)] = r[a * 4 + b];
    }
    __syncthreads();
    {   // inverse of fwd pass 1
        const int g = tid >> 4, j = tid & 15, base = g * 256 + j;
        #pragma unroll
        for (int a = 0; a < 4; a++)
            #pragma unroll
            for (int b = 0; b < 4; b++) r[a * 4 + b] = S[sphys(base + a * 64 + b * 16)];
        inv_pass<16, 16, 0>(r, j);
        #pragma unroll
        for (int a = 0; a < 4; a++)
            #pragma unroll
            for (int b = 0; b < 4; b++) S[sphys(base + a * 64 + b * 16)] = r[a * 4 + b];
    }
    __syncthreads();
    {   // inverse of fwd pass 0; results land in natural order, keep idx < 2048
        #pragma unroll
        for (int a = 0; a < 4; a++)
            #pragma unroll
            for (int b = 0; b < 4; b++) r[a * 4 + b] = S[sphys(tid + a * 1024 + b * 256)];
        inv_pass<256, 1, 0>(r, tid);
        const float inv = 1.0f / (float)NFFT;
        float* up = g_Ubig + (size_t)(k * D_DIM + d) * L_SEQ;
        float* um = g_Ubig + (size_t)(C_CONV / 2 + k * D_DIM + d) * L_SEQ;
        #pragma unroll
        for (int a = 0; a < 2; a++)
            #pragma unroll
            for (int b = 0; b < 4; b++) {
                int idx = tid + a * 1024 + b * 256;
                float2 v = r[a * 4 + b];
                up[idx] = to_tf32(v.x * inv);
                um[idx] = to_tf32(((idx & 1) ? -v.y : v.y) * inv);
            }
    }
}

// ---- AR channels via coalesced 32x32 transpose tiles ----
__global__ void k_arfill(const float* __restrict__ x) {
    __shared__ float T[32][33];
    const int tx = threadIdx.x, ty = threadIdx.y;
    const int lb = blockIdx.x * 32, cb = blockIdx.y * 32;
    const int i = cb / D_DIM, d0 = cb - i * D_DIM;
    #pragma unroll
    for (int rr = 0; rr < 4; rr++) {
        int l = lb + ty + rr * 8;
        T[ty + rr * 8][tx] = (l >= i) ? x[(size_t)(l - i) * D_DIM + d0 + tx] : 0.0f;
    }
    __syncthreads();
    #pragma unroll
    for (int rr = 0; rr < 4; rr++) {
        int cl = ty + rr * 8;
        g_Ubig[(size_t)(C_CONV + cb + cl) * L_SEQ + lb + tx] = to_tf32(T[tx][cl]);
    }
}

// ---- pack [Mp*sig4 ; Mm*sig4 ; Mu] (tf32-rounded) ----
__global__ void __launch_bounds__(256) k_mbig(const float* __restrict__ Mp,
                                              const float* __restrict__ Mm,
                                              const float* __restrict__ Mu,
                                              const float* __restrict__ sigma) {
    int c = blockIdx.x;
    const float* src; float scale;
    if (c < K_F * D_DIM) {
        src = Mp + (size_t)c * D_DIM; scale = powf(sigma[c / D_DIM], 0.25f);
    } else if (c < 2 * K_F * D_DIM) {
        int cc = c - K_F * D_DIM;
        src = Mm + (size_t)cc * D_DIM; scale = powf(sigma[cc / D_DIM], 0.25f);
    } else {
        src = Mu + (size_t)(c - 2 * K_F * D_DIM) * D_DIM; scale = 1.0f;
    }
    for (int o = threadIdx.x; o < D_DIM; o += 256)
        g_Mbig[(size_t)c * D_DIM + o] = to_tf32(src[o] * scale);
}

// ---- TF32 GEMM: 128x96 block, 4 warps (64x48 each), double-buffered 16-k slabs ----
__device__ __forceinline__ void mma_tf32(float* acc, const uint32_t* a, const uint32_t* b) {
    asm volatile(
        "mma.sync.aligned.m16n8k8.row.col.f32.tf32.tf32.f32 "
        "{%0,%1,%2,%3}, {%4,%5,%6,%7}, {%8,%9}, {%0,%1,%2,%3};"
        : "+f"(acc[0]), "+f"(acc[1]), "+f"(acc[2]), "+f"(acc[3])
        : "r"(a[0]), "r"(a[1]), "r"(a[2]), "r"(a[3]), "r"(b[0]), "r"(b[1]));
}

__global__ void __launch_bounds__(128) k_gemm(float* __restrict__ out) {
    __shared__ float As[2][16][136];
    __shared__ float Bs[2][16][104];
    const int tid = threadIdx.x, lane = tid & 31, warp = tid >> 5;
    const int mbase = blockIdx.y * 128, nbase = blockIdx.x * 96;
    const int wm = (warp & 1) * 64, wn = (warp >> 1) * 48;
    const int row = lane >> 2, col = lane & 3;
    const int lc = tid >> 3, lq = (tid & 7) * 4;

    float acc[4][6][4];
    #pragma unroll
    for (int mi = 0; mi < 4; mi++)
        #pragma unroll
        for (int ni = 0; ni < 6; ni++)
            #pragma unroll
            for (int q = 0; q < 4; q++) acc[mi][ni][q] = 0.0f;

    float4 ra[4], rb[3];
    auto LOADG = [&](int kt) {
        size_t kb = (size_t)(kt * 16 + lc);
        #pragma unroll
        for (int i = 0; i < 4; i++)
            ra[i] = *(const float4*)(g_Ubig + kb * L_SEQ + mbase + i * 32 + lq);
        #pragma unroll
        for (int i = 0; i < 3; i++)
            rb[i] = *(const float4*)(g_Mbig + kb * D_DIM + nbase + i * 32 + lq);
    };
    auto STORES = [&](int bf) {
        #pragma unroll
        for (int i = 0; i < 4; i++) *(float4*)&As[bf][lc][i * 32 + lq] = ra[i];
        #pragma unroll
        for (int i = 0; i < 3; i++) *(float4*)&Bs[bf][lc][i * 32 + lq] = rb[i];
    };

    LOADG(0); STORES(0); __syncthreads();

    for (int kt = 0; kt < NKT; kt++) {
        const int bf = kt & 1;
        if (kt + 1 < NKT) LOADG(kt + 1);
        #pragma unroll
        for (int ks = 0; ks < 2; ks++) {
            const int k8 = ks * 8;
            uint32_t a[4][4], b[6][2];
            #pragma unroll
            for (int mi = 0; mi < 4; mi++) {
                int lb2 = wm + mi * 16 + row;
                a[mi][0] = __float_as_uint(As[bf][k8 + col][lb2]);
                a[mi][1] = __float_as_uint(As[bf][k8 + col][lb2 + 8]);
                a[mi][2] = __float_as_uint(As[bf][k8 + col + 4][lb2]);
                a[mi][3] = __float_as_uint(As[bf][k8 + col + 4][lb2 + 8]);
            }
            #pragma unroll
            for (int ni = 0; ni < 6; ni++) {
                int nb = wn + ni * 8 + row;
                b[ni][0] = __float_as_uint(Bs[bf][k8 + col][nb]);
                b[ni][1] = __float_as_uint(Bs[bf][k8 + col + 4][nb]);
            }
            #pragma unroll
            for (int mi = 0; mi < 4; mi++)
                #pragma unroll
                for (int ni = 0; ni < 6; ni++)
                    mma_tf32(acc[mi][ni], a[mi], b[ni]);
        }
        if (kt + 1 < NKT) STORES(bf ^ 1);
        __syncthreads();
    }

    #pragma unroll
    for (int mi = 0; mi < 4; mi++)
        #pragma unroll
        for (int ni = 0; ni < 6; ni++) {
            int r0 = mbase + wm + mi * 16 + row;
            int c0 = nbase + wn + ni * 8 + col * 2;
            out[(size_t)r0 * D_DIM + c0]           = acc[mi][ni][0];
            out[(size_t)r0 * D_DIM + c0 + 1]       = acc[mi][ni][1];
            out[(size_t)(r0 + 8) * D_DIM + c0]     = acc[mi][ni][2];
            out[(size_t)(r0 + 8) * D_DIM + c0 + 1] = acc[mi][ni][3];
        }
}

extern "C" void kernel_launch(void* const* d_in, const int* in_sizes, int n_in,
                              void* d_out, int out_size) {
    const float* x     = (const float*)d_in[0];
    const float* phi   = (const float*)d_in[1];
    const float* sigma = (const float*)d_in[2];
    const float* Mp    = (const float*)d_in[3];
    const float* Mm    = (const float*)d_in[4];
    const float* Mu    = (const float*)d_in[5];
    (void)in_sizes; (void)n_in; (void)out_size;

    k_twiddle<<<NFFT / 256, 256>>>();
    k_fft_fwd<<<D_DIM + K_F, 256>>>(x, phi);
    k_conv_inv<<<K_F * D_DIM, 256>>>();
    k_arfill<<<dim3(L_SEQ / 32, KU * D_DIM / 32), dim3(32, 8)>>>(x);
    k_mbig<<<C_TOT, 256>>>(Mp, Mm, Mu, sigma);
    k_gemm<<<dim3(D_DIM / 96, L_SEQ / 128), 128>>>((float*)d_out);
}

// round 7
// speedup vs baseline: 1.2594x; 1.2594x over previous
#include <cuda_runtime.h>
#include <cstdint>

#define L_SEQ 2048
#define D_DIM 768
#define K_F   16
#define NFFT  4096
#define KU    3
#define C_CONV (2 * K_F * D_DIM)          // 24576
#define C_TOT  (C_CONV + KU * D_DIM)      // 26880
#define NKT    (C_TOT / 16)               // 1680

__device__ __align__(16) float  g_Ubig[(size_t)C_TOT * L_SEQ];   // (C, L), tf32-rounded
__device__ __align__(16) float  g_Mbig[(size_t)C_TOT * D_DIM];   // (C, O), tf32-rounded
__device__ __align__(16) float2 g_Z[D_DIM * NFFT];
__device__ __align__(16) float2 g_V[K_F * NFFT];
__device__ __align__(16) float2 g_tw[NFFT];

__device__ __forceinline__ float2 cadd(float2 a, float2 b) { return make_float2(a.x + b.x, a.y + b.y); }
__device__ __forceinline__ float2 csub(float2 a, float2 b) { return make_float2(a.x - b.x, a.y - b.y); }
__device__ __forceinline__ float2 cmul(float2 a, float2 b) {
    return make_float2(a.x * b.x - a.y * b.y, a.x * b.y + a.y * b.x);
}
__device__ __forceinline__ float2 cmulconj(float2 a, float2 w) {
    return make_float2(a.x * w.x + a.y * w.y, a.y * w.x - a.x * w.y);
}
__device__ __forceinline__ float to_tf32(float x) {
    float r; asm("cvt.rna.tf32.f32 %0, %1;" : "=f"(r) : "f"(x)); return r;
}
__device__ __forceinline__ int sphys(int i) { return i + (i >> 4) + (i >> 8); }
#define SMEM_FFT 4368

__global__ void k_twiddle() {
    int j = blockIdx.x * blockDim.x + threadIdx.x;
    if (j < NFFT) {
        float s, c;
        sincospif(-2.0f * (float)j / (float)NFFT, &s, &c);
        g_tw[j] = make_float2(c, s);
    }
}

// ---- radix-4 butterflies ----
__device__ __forceinline__ void bf4_dif(float2& e0, float2& e1, float2& e2, float2& e3,
                                        float2 w1, float2 w2, float2 w3) {
    float2 t0 = cadd(e0, e2), t1 = csub(e0, e2);
    float2 t2 = cadd(e1, e3), t3 = csub(e1, e3);
    float2 t3m = make_float2(t3.y, -t3.x);
    e0 = cadd(t0, t2); e1 = cmul(cadd(t1, t3m), w1);
    e2 = cmul(csub(t0, t2), w2); e3 = cmul(csub(t1, t3m), w3);
}
__device__ __forceinline__ void bf4_dif_nw(float2& e0, float2& e1, float2& e2, float2& e3) {
    float2 t0 = cadd(e0, e2), t1 = csub(e0, e2);
    float2 t2 = cadd(e1, e3), t3 = csub(e1, e3);
    float2 t3m = make_float2(t3.y, -t3.x);
    e0 = cadd(t0, t2); e1 = cadd(t1, t3m); e2 = csub(t0, t2); e3 = csub(t1, t3m);
}
__device__ __forceinline__ void bf4_dit(float2& e0, float2& e1, float2& e2, float2& e3,
                                        float2 w1, float2 w2, float2 w3) {
    float2 u1 = cmulconj(e1, w1), u2 = cmulconj(e2, w2), u3 = cmulconj(e3, w3);
    float2 t0 = cadd(e0, u2), t1 = csub(e0, u2);
    float2 t2 = cadd(u1, u3), t3 = csub(u1, u3);
    float2 it3 = make_float2(-t3.y, t3.x);
    e0 = cadd(t0, t2); e1 = cadd(t1, it3); e2 = csub(t0, t2); e3 = csub(t1, it3);
}
__device__ __forceinline__ void bf4_dit_nw(float2& e0, float2& e1, float2& e2, float2& e3) {
    float2 t0 = cadd(e0, e2), t1 = csub(e0, e2);
    float2 t2 = cadd(e1, e3), t3 = csub(e1, e3);
    float2 it3 = make_float2(-t3.y, t3.x);
    e0 = cadd(t0, t2); e1 = cadd(t1, it3); e2 = csub(t0, t2); e3 = csub(t1, it3);
}

template <int Q2, int STEP, int HT>
__device__ __forceinline__ void fwd_pass(float2* r, int j) {
    #pragma unroll
    for (int b = 0; b < 4; b++) {
        float2 w1 = g_tw[(j + b * Q2) * STEP];
        float2 w2 = cmul(w1, w1), w3 = cmul(w2, w1);
        bf4_dif(r[b], r[4 + b], r[8 + b], r[12 + b], w1, w2, w3);
    }
    if (HT) {
        #pragma unroll
        for (int a = 0; a < 4; a++) bf4_dif_nw(r[4 * a], r[4 * a + 1], r[4 * a + 2], r[4 * a + 3]);
    } else {
        float2 w1 = g_tw[j * STEP * 4];
        float2 w2 = cmul(w1, w1), w3 = cmul(w2, w1);
        #pragma unroll
        for (int a = 0; a < 4; a++) bf4_dif(r[4 * a], r[4 * a + 1], r[4 * a + 2], r[4 * a + 3], w1, w2, w3);
    }
}
template <int Q2, int STEP, int HT>
__device__ __forceinline__ void inv_pass(float2* r, int j) {
    if (HT) {
        #pragma unroll
        for (int a = 0; a < 4; a++) bf4_dit_nw(r[4 * a], r[4 * a + 1], r[4 * a + 2], r[4 * a + 3]);
    } else {
        float2 w1 = g_tw[j * STEP * 4];
        float2 w2 = cmul(w1, w1), w3 = cmul(w2, w1);
        #pragma unroll
        for (int a = 0; a < 4; a++) bf4_dit(r[4 * a], r[4 * a + 1], r[4 * a + 2], r[4 * a + 3], w1, w2, w3);
    }
    #pragma unroll
    for (int b = 0; b < 4; b++) {
        float2 w1 = g_tw[(j + b * Q2) * STEP];
        float2 w2 = cmul(w1, w1), w3 = cmul(w2, w1);
        bf4_dit(r[b], r[4 + b], r[8 + b], r[12 + b], w1, w2, w3);
    }
}

// ---- forward FFT: 768 packed x-channels + 16 phi-channels, 3 register passes ----
__global__ void __launch_bounds__(256) k_fft_fwd(const float* __restrict__ x,
                                                 const float* __restrict__ phi) {
    __shared__ float2 S[SMEM_FFT];
    const int blk = blockIdx.x, tid = threadIdx.x;
    float2 r[16];
    #pragma unroll
    for (int a = 0; a < 4; a++)
        #pragma unroll
        for (int b = 0; b < 4; b++) {
            int idx = tid + a * 1024 + b * 256;
            if (blk < D_DIM) {
                float v = (idx < L_SEQ) ? __ldg(x + (size_t)idx * D_DIM + blk) : 0.0f;
                r[a * 4 + b] = make_float2(v, (idx & 1) ? -v : v);
            } else {
                float v = (idx < L_SEQ) ? __ldg(phi + (size_t)idx * K_F + (blk - D_DIM)) : 0.0f;
                r[a * 4 + b] = make_float2(v, 0.0f);
            }
        }
    fwd_pass<256, 1, 0>(r, tid);
    #pragma unroll
    for (int a = 0; a < 4; a++)
        #pragma unroll
        for (int b = 0; b < 4; b++) S[sphys(tid + a * 1024 + b * 256)] = r[a * 4 + b];
    __syncthreads();
    {
        const int g = tid >> 4, j = tid & 15, base = g * 256 + j;
        #pragma unroll
        for (int a = 0; a < 4; a++)
            #pragma unroll
            for (int b = 0; b < 4; b++) r[a * 4 + b] = S[sphys(base + a * 64 + b * 16)];
        fwd_pass<16, 16, 0>(r, j);
        #pragma unroll
        for (int a = 0; a < 4; a++)
            #pragma unroll
            for (int b = 0; b < 4; b++) S[sphys(base + a * 64 + b * 16)] = r[a * 4 + b];
    }
    __syncthreads();
    {
        const int base = tid * 16;
        #pragma unroll
        for (int a = 0; a < 4; a++)
            #pragma unroll
            for (int b = 0; b < 4; b++) r[a * 4 + b] = S[sphys(base + a * 4 + b)];
        fwd_pass<1, 256, 1>(r, 0);
        #pragma unroll
        for (int a = 0; a < 4; a++)
            #pragma unroll
            for (int b = 0; b < 4; b++) S[sphys(base + a * 4 + b)] = r[a * 4 + b];
    }
    __syncthreads();
    float2* out = (blk < D_DIM) ? (g_Z + (size_t)blk * NFFT) : (g_V + (size_t)(blk - D_DIM) * NFFT);
    for (int t = tid; t < NFFT; t += 256) out[t] = S[sphys(t)];
}

// ---- per-(k,d): pointwise V*Z then inverse FFT (3 register passes), write tf32 ----
__global__ void __launch_bounds__(256) k_conv_inv() {
    __shared__ float2 S[SMEM_FFT];
    const int blk = blockIdx.x;
    const int k = blk / D_DIM, d = blk - k * D_DIM;
    const int tid = threadIdx.x;
    const float2* Z = g_Z + (size_t)d * NFFT;
    const float2* V = g_V + (size_t)k * NFFT;
    for (int t = tid; t < NFFT; t += 256) S[sphys(t)] = cmul(Z[t], V[t]);
    __syncthreads();
    float2 r[16];
    {
        const int base = tid * 16;
        #pragma unroll
        for (int a = 0; a < 4; a++)
            #pragma unroll
            for (int b = 0; b < 4; b++) r[a * 4 + b] = S[sphys(base + a * 4 + b)];
        inv_pass<1, 256, 1>(r, 0);
        #pragma unroll
        for (int a = 0; a < 4; a++)
            #pragma unroll
            for (int b = 0; b < 4; b++) S[sphys(base + a * 4 + b)] = r[a * 4 + b];
    }
    __syncthreads();
    {
        const int g = tid >> 4, j = tid & 15, base = g * 256 + j;
        #pragma unroll
        for (int a = 0; a < 4; a++)
            #pragma unroll
            for (int b = 0; b < 4; b++) r[a * 4 + b] = S[sphys(base + a * 64 + b * 16)];
        inv_pass<16, 16, 0>(r, j);
        #pragma unroll
        for (int a = 0; a < 4; a++)
            #pragma unroll
            for (int b = 0; b < 4; b++) S[sphys(base + a * 64 + b * 16)] = r[a * 4 + b];
    }
    __syncthreads();
    {
        #pragma unroll
        for (int a = 0; a < 4; a++)
            #pragma unroll
            for (int b = 0; b < 4; b++) r[a * 4 + b] = S[sphys(tid + a * 1024 + b * 256)];
        inv_pass<256, 1, 0>(r, tid);
        const float inv = 1.0f / (float)NFFT;
        float* up = g_Ubig + (size_t)(k * D_DIM + d) * L_SEQ;
        float* um = g_Ubig + (size_t)(C_CONV / 2 + k * D_DIM + d) * L_SEQ;
        #pragma unroll
        for (int a = 0; a < 2; a++)
            #pragma unroll
            for (int b = 0; b < 4; b++) {
                int idx = tid + a * 1024 + b * 256;
                float2 v = r[a * 4 + b];
                up[idx] = to_tf32(v.x * inv);
                um[idx] = to_tf32(((idx & 1) ? -v.y : v.y) * inv);
            }
    }
}

// ---- AR channels via coalesced 32x32 transpose tiles ----
__global__ void k_arfill(const float* __restrict__ x) {
    __shared__ float T[32][33];
    const int tx = threadIdx.x, ty = threadIdx.y;
    const int lb = blockIdx.x * 32, cb = blockIdx.y * 32;
    const int i = cb / D_DIM, d0 = cb - i * D_DIM;
    #pragma unroll
    for (int rr = 0; rr < 4; rr++) {
        int l = lb + ty + rr * 8;
        T[ty + rr * 8][tx] = (l >= i) ? x[(size_t)(l - i) * D_DIM + d0 + tx] : 0.0f;
    }
    __syncthreads();
    #pragma unroll
    for (int rr = 0; rr < 4; rr++) {
        int cl = ty + rr * 8;
        g_Ubig[(size_t)(C_CONV + cb + cl) * L_SEQ + lb + tx] = to_tf32(T[tx][cl]);
    }
}

// ---- pack [Mp*sig4 ; Mm*sig4 ; Mu] (tf32-rounded) ----
__global__ void __launch_bounds__(256) k_mbig(const float* __restrict__ Mp,
                                              const float* __restrict__ Mm,
                                              const float* __restrict__ Mu,
                                              const float* __restrict__ sigma) {
    int c = blockIdx.x;
    const float* src; float scale;
    if (c < K_F * D_DIM) {
        src = Mp + (size_t)c * D_DIM; scale = powf(sigma[c / D_DIM], 0.25f);
    } else if (c < 2 * K_F * D_DIM) {
        int cc = c - K_F * D_DIM;
        src = Mm + (size_t)cc * D_DIM; scale = powf(sigma[cc / D_DIM], 0.25f);
    } else {
        src = Mu + (size_t)(c - 2 * K_F * D_DIM) * D_DIM; scale = 1.0f;
    }
    for (int o = threadIdx.x; o < D_DIM; o += 256)
        g_Mbig[(size_t)c * D_DIM + o] = to_tf32(src[o] * scale);
}

// ---- TF32 GEMM: 128x96 block, 256 threads / 8 warps (32x48 each), cp.async double buffer ----
__device__ __forceinline__ void mma_tf32(float* acc, const uint32_t* a, const uint32_t* b) {
    asm volatile(
        "mma.sync.aligned.m16n8k8.row.col.f32.tf32.tf32.f32 "
        "{%0,%1,%2,%3}, {%4,%5,%6,%7}, {%8,%9}, {%0,%1,%2,%3};"
        : "+f"(acc[0]), "+f"(acc[1]), "+f"(acc[2]), "+f"(acc[3])
        : "r"(a[0]), "r"(a[1]), "r"(a[2]), "r"(a[3]), "r"(b[0]), "r"(b[1]));
}
__device__ __forceinline__ void cp16(uint32_t dst, const float* src) {
    asm volatile("cp.async.cg.shared.global [%0], [%1], 16;" :: "r"(dst), "l"(src));
}

__global__ void __launch_bounds__(256) k_gemm(float* __restrict__ out) {
    __shared__ float As[2][16][136];   // pitch 544B (16B aligned)
    __shared__ float Bs[2][16][104];   // pitch 416B (16B aligned)
    const int tid = threadIdx.x, lane = tid & 31, warp = tid >> 5;
    const int mbase = blockIdx.y * 128, nbase = blockIdx.x * 96;
    const int wm = (warp & 3) * 32, wn = (warp >> 2) * 48;
    const int row = lane >> 2, col = lane & 3;

    float acc[2][6][4];
    #pragma unroll
    for (int mi = 0; mi < 2; mi++)
        #pragma unroll
        for (int ni = 0; ni < 6; ni++)
            #pragma unroll
            for (int q = 0; q < 4; q++) acc[mi][ni][q] = 0.0f;

    auto PREFETCH = [&](int kt, int bf) {
        size_t kb = (size_t)kt * 16;
        // A: 16 rows x 128 floats = 512 float4; 2 per thread
        #pragma unroll
        for (int i = 0; i < 2; i++) {
            int idx = tid + i * 256;
            int rA = idx >> 5, c4 = (idx & 31) * 4;
            cp16((uint32_t)__cvta_generic_to_shared(&As[bf][rA][c4]),
                 g_Ubig + (kb + rA) * L_SEQ + mbase + c4);
        }
        // B: 16 rows x 96 floats = 384 float4; threads 0..191 do 2
        #pragma unroll
        for (int i = 0; i < 2; i++) {
            int idx = tid + i * 192;
            if (tid < 192) {
                int rB = idx / 24, c4 = (idx % 24) * 4;
                cp16((uint32_t)__cvta_generic_to_shared(&Bs[bf][rB][c4]),
                     g_Mbig + (kb + rB) * D_DIM + nbase + c4);
            }
        }
        asm volatile("cp.async.commit_group;");
    };

    PREFETCH(0, 0);

    for (int kt = 0; kt < NKT; kt++) {
        const int bf = kt & 1;
        if (kt + 1 < NKT) {
            PREFETCH(kt + 1, bf ^ 1);
            asm volatile("cp.async.wait_group 1;");
        } else {
            asm volatile("cp.async.wait_group 0;");
        }
        __syncthreads();
        #pragma unroll
        for (int ks = 0; ks < 2; ks++) {
            const int k8 = ks * 8;
            uint32_t a[2][4], b[6][2];
            #pragma unroll
            for (int mi = 0; mi < 2; mi++) {
                int lb2 = wm + mi * 16 + row;
                a[mi][0] = __float_as_uint(As[bf][k8 + col][lb2]);
                a[mi][1] = __float_as_uint(As[bf][k8 + col][lb2 + 8]);
                a[mi][2] = __float_as_uint(As[bf][k8 + col + 4][lb2]);
                a[mi][3] = __float_as_uint(As[bf][k8 + col + 4][lb2 + 8]);
            }
            #pragma unroll
            for (int ni = 0; ni < 6; ni++) {
                int nb = wn + ni * 8 + row;
                b[ni][0] = __float_as_uint(Bs[bf][k8 + col][nb]);
                b[ni][1] = __float_as_uint(Bs[bf][k8 + col + 4][nb]);
            }
            #pragma unroll
            for (int mi = 0; mi < 2; mi++)
                #pragma unroll
                for (int ni = 0; ni < 6; ni++)
                    mma_tf32(acc[mi][ni], a[mi], b[ni]);
        }
        __syncthreads();
    }

    #pragma unroll
    for (int mi = 0; mi < 2; mi++)
        #pragma unroll
        for (int ni = 0; ni < 6; ni++) {
            int r0 = mbase + wm + mi * 16 + row;
            int c0 = nbase + wn + ni * 8 + col * 2;
            out[(size_t)r0 * D_DIM + c0]           = acc[mi][ni][0];
            out[(size_t)r0 * D_DIM + c0 + 1]       = acc[mi][ni][1];
            out[(size_t)(r0 + 8) * D_DIM + c0]     = acc[mi][ni][2];
            out[(size_t)(r0 + 8) * D_DIM + c0 + 1] = acc[mi][ni][3];
        }
}

extern "C" void kernel_launch(void* const* d_in, const int* in_sizes, int n_in,
                              void* d_out, int out_size) {
    const float* x     = (const float*)d_in[0];
    const float* phi   = (const float*)d_in[1];
    const float* sigma = (const float*)d_in[2];
    const float* Mp    = (const float*)d_in[3];
    const float* Mm    = (const float*)d_in[4];
    const float* Mu    = (const float*)d_in[5];
    (void)in_sizes; (void)n_in; (void)out_size;

    k_twiddle<<<NFFT / 256, 256>>>();
    k_fft_fwd<<<D_DIM + K_F, 256>>>(x, phi);
    k_conv_inv<<<K_F * D_DIM, 256>>>();
    k_arfill<<<dim3(L_SEQ / 32, KU * D_DIM / 32), dim3(32, 8)>>>(x);
    k_mbig<<<C_TOT, 256>>>(Mp, Mm, Mu, sigma);
    k_gemm<<<dim3(D_DIM / 96, L_SEQ / 128), 256>>>((float*)d_out);
}